// round 4
// baseline (speedup 1.0000x reference)
#include <cuda_runtime.h>

// Problem constants
#define Bsz 1024
#define Nn  256
#define Dd  64
#define LAT 128
#define EC  32
#define KT  64              // k-tile per pass
#define NPASS (LAT / KT)    // 2
#define NTHREADS 512

// Shared layout strides (floats)
#define SAT_STRIDE 258   // A^T[d][n]  (even -> 8B-aligned n-pairs; banks (2d+n)%32)
#define SET_STRIDE 258   // Ecomm^T[e][n]
#define W2_STRIDE  132   // duplicated weights [row][2k] (mult of 4 -> 16B aligned)
#define SL_STRIDE  65    // logits/att [n][kt]

struct SmemT {
    float sAT[Dd * SAT_STRIDE];   // 16512 : neighbor[b] transposed (persistent)
    float sET[EC * SET_STRIDE];   //  8256 : relu(A@Wc+bc) transposed (persistent)
    float sWf2[Dd * W2_STRIDE];   //  8448 : dup weights (Wc ph2 / Wf tile) + ph4 scratch
    float sWa2[EC * W2_STRIDE];   //  4224 : dup Wa2 tile, then agg-reduce scratch
    float sL[Nn * SL_STRIDE];     // 16640 : logit tile -> att (in place)
    float sbc[EC];
    float sbf[KT];
    float sAgg[LAT];
    float sRedA[8 * 65];
    float sRedB[8 * 65];
};
// total = 55344 floats = 221376 bytes (< 227KB)

typedef unsigned long long u64;

__device__ __forceinline__ void unpack2(u64 v, float& lo, float& hi) {
    asm("mov.b64 {%0, %1}, %2;" : "=f"(lo), "=f"(hi) : "l"(v));
}
__device__ __forceinline__ u64 pack2(float a, float b) {
    u64 r;
    asm("mov.b64 %0, {%1, %2};" : "=l"(r) : "f"(a), "f"(b));
    return r;
}
// Packed fp32x2 FMA (Blackwell FFMA2): 2x fp32 FMA throughput.
__device__ __forceinline__ void ffma2(u64& d, u64 a, u64 b) {
    asm("fma.rn.f32x2 %0, %1, %2, %0;" : "+l"(d) : "l"(a), "l"(b));
}

__global__ void __launch_bounds__(NTHREADS, 1)
arm_fused_kernel(const float* __restrict__ nb,   // [B,N,D]
                 const float* __restrict__ Wc,   // [D,EC]
                 const float* __restrict__ bc,   // [EC]
                 const float* __restrict__ Wf,   // [D,LAT]
                 const float* __restrict__ bf,   // [LAT]
                 const float* __restrict__ Wa,   // [3EC,LAT] (rows EC..2EC-1 only)
                 const float* __restrict__ Wl,   // [LAT,LAT]
                 const float* __restrict__ bl,   // [LAT]
                 float* __restrict__ out)        // [B,LAT]
{
    extern __shared__ float smem_raw[];
    SmemT* S = reinterpret_cast<SmemT*>(smem_raw);

    const int t = threadIdx.x;
    const int b = blockIdx.x;

    // ---------------- Phase 1: load A transposed + Wc(dup) + bc ----------------
    {
        const float4* nb4 = reinterpret_cast<const float4*>(nb + (size_t)b * Nn * Dd);
        #pragma unroll
        for (int r = 0; r < 8; ++r) {
            int fi = t + r * NTHREADS;          // 0..4095 float4 indices
            int n  = fi >> 4;
            int d  = (fi & 15) * 4;
            float4 v = nb4[fi];
            S->sAT[(d + 0) * SAT_STRIDE + n] = v.x;
            S->sAT[(d + 1) * SAT_STRIDE + n] = v.y;
            S->sAT[(d + 2) * SAT_STRIDE + n] = v.z;
            S->sAT[(d + 3) * SAT_STRIDE + n] = v.w;
        }
        // Wc (64x32) duplicated into sWf2[d][2e]
        #pragma unroll
        for (int r = 0; r < 4; ++r) {
            int li = t + r * NTHREADS;          // 0..2047
            int d  = li >> 5;
            int e  = li & 31;
            float w = Wc[d * EC + e];
            *reinterpret_cast<u64*>(&S->sWf2[d * W2_STRIDE + 2 * e]) = pack2(w, w);
        }
        if (t < EC) S->sbc[t] = bc[t];
    }
    __syncthreads();

    // ---------------- Phase 2: Ecomm^T = relu(A@Wc+bc)^T  [32e x 256n] ----------------
    {
        const int e0 = (t & 7) * 4;             // 8 e-groups
        const int n0 = (t >> 3) * 4;            // 64 n-groups (2 n-pairs each)
        u64 acc[2][4];
        #pragma unroll
        for (int p = 0; p < 2; ++p)
            #pragma unroll
            for (int j = 0; j < 4; ++j) acc[p][j] = 0ull;

        #pragma unroll 4
        for (int d = 0; d < Dd; ++d) {
            u64 a0 = *reinterpret_cast<const u64*>(&S->sAT[d * SAT_STRIDE + n0]);
            u64 a1 = *reinterpret_cast<const u64*>(&S->sAT[d * SAT_STRIDE + n0 + 2]);
            ulonglong2 wA = *reinterpret_cast<const ulonglong2*>(&S->sWf2[d * W2_STRIDE + 2 * e0]);
            ulonglong2 wB = *reinterpret_cast<const ulonglong2*>(&S->sWf2[d * W2_STRIDE + 2 * e0 + 4]);
            ffma2(acc[0][0], a0, wA.x); ffma2(acc[0][1], a0, wA.y);
            ffma2(acc[0][2], a0, wB.x); ffma2(acc[0][3], a0, wB.y);
            ffma2(acc[1][0], a1, wA.x); ffma2(acc[1][1], a1, wA.y);
            ffma2(acc[1][2], a1, wB.x); ffma2(acc[1][3], a1, wB.y);
        }
        #pragma unroll
        for (int j = 0; j < 4; ++j) {
            float bcj = S->sbc[e0 + j];
            #pragma unroll
            for (int p = 0; p < 2; ++p) {
                float v0, v1;
                unpack2(acc[p][j], v0, v1);
                u64 rv = pack2(fmaxf(v0 + bcj, 0.f), fmaxf(v1 + bcj, 0.f));
                *reinterpret_cast<u64*>(&S->sET[(e0 + j) * SET_STRIDE + n0 + 2 * p]) = rv;
            }
        }
    }
    __syncthreads();

    // ---------------- Phase 3: 2 passes over LAT in tiles of 64 ----------------
    const int ktx = t & 15;          // 16 k-groups of 4
    const int kt0 = ktx * 4;
    const int n0f = (t >> 4) * 8;    // 32 n-groups of 8 (4 pairs)
    const int tyf = t >> 4;
    const int kq = t & 63;           // softmax column
    const int g  = t >> 6;           // softmax n-group (8 x 32 rows)

    for (int kp = 0; kp < NPASS; ++kp) {
        const int k0 = kp * KT;

        // 3a: stage duplicated Wf tile (64x64), Wa2 tile (32x64), bf tile
        #pragma unroll
        for (int r = 0; r < 8; ++r) {
            int li = t + r * NTHREADS;          // 0..4095
            int d  = li >> 6;
            int kk = li & 63;
            float w = Wf[d * LAT + k0 + kk];
            *reinterpret_cast<u64*>(&S->sWf2[d * W2_STRIDE + 2 * kk]) = pack2(w, w);
        }
        #pragma unroll
        for (int r = 0; r < 4; ++r) {
            int li = t + r * NTHREADS;          // 0..2047
            int e  = li >> 6;
            int kk = li & 63;
            float w = Wa[(EC + e) * LAT + k0 + kk];
            *reinterpret_cast<u64*>(&S->sWa2[e * W2_STRIDE + 2 * kk]) = pack2(w, w);
        }
        if (t < KT) S->sbf[t] = bf[k0 + t];
        __syncthreads();

        // 3b: logit tile L = Ecomm @ Wa2_tile  [256 x 64] (bias/self/mean cancel)
        {
            u64 acc[4][4];
            #pragma unroll
            for (int p = 0; p < 4; ++p)
                #pragma unroll
                for (int j = 0; j < 4; ++j) acc[p][j] = 0ull;

            #pragma unroll 4
            for (int e = 0; e < EC; ++e) {
                u64 a0 = *reinterpret_cast<const u64*>(&S->sET[e * SET_STRIDE + n0f]);
                u64 a1 = *reinterpret_cast<const u64*>(&S->sET[e * SET_STRIDE + n0f + 2]);
                u64 a2 = *reinterpret_cast<const u64*>(&S->sET[e * SET_STRIDE + n0f + 4]);
                u64 a3 = *reinterpret_cast<const u64*>(&S->sET[e * SET_STRIDE + n0f + 6]);
                ulonglong2 wA = *reinterpret_cast<const ulonglong2*>(&S->sWa2[e * W2_STRIDE + 8 * ktx]);
                ulonglong2 wB = *reinterpret_cast<const ulonglong2*>(&S->sWa2[e * W2_STRIDE + 8 * ktx + 4]);
                ffma2(acc[0][0], a0, wA.x); ffma2(acc[0][1], a0, wA.y);
                ffma2(acc[0][2], a0, wB.x); ffma2(acc[0][3], a0, wB.y);
                ffma2(acc[1][0], a1, wA.x); ffma2(acc[1][1], a1, wA.y);
                ffma2(acc[1][2], a1, wB.x); ffma2(acc[1][3], a1, wB.y);
                ffma2(acc[2][0], a2, wA.x); ffma2(acc[2][1], a2, wA.y);
                ffma2(acc[2][2], a2, wB.x); ffma2(acc[2][3], a2, wB.y);
                ffma2(acc[3][0], a3, wA.x); ffma2(acc[3][1], a3, wA.y);
                ffma2(acc[3][2], a3, wB.x); ffma2(acc[3][3], a3, wB.y);
            }
            #pragma unroll
            for (int p = 0; p < 4; ++p)
                #pragma unroll
                for (int j = 0; j < 4; ++j) {
                    float v0, v1;
                    unpack2(acc[p][j], v0, v1);
                    S->sL[(n0f + 2 * p)     * SL_STRIDE + kt0 + j] = v0;
                    S->sL[(n0f + 2 * p + 1) * SL_STRIDE + kt0 + j] = v1;
                }
        }
        __syncthreads();

        // 3c: per-column softmax over n=256, att written back in place
        {
            float lv[32];
            float m = -1e30f;
            #pragma unroll
            for (int i = 0; i < 32; ++i) {
                lv[i] = S->sL[(g * 32 + i) * SL_STRIDE + kq];
                m = fmaxf(m, lv[i]);
            }
            S->sRedA[g * 65 + kq] = m;
            __syncthreads();
            #pragma unroll
            for (int j = 0; j < 8; ++j) m = fmaxf(m, S->sRedA[j * 65 + kq]);

            float s = 0.f;
            #pragma unroll
            for (int i = 0; i < 32; ++i) {
                lv[i] = __expf(lv[i] - m);
                s += lv[i];
            }
            S->sRedB[g * 65 + kq] = s;
            __syncthreads();
            float St = 0.f;
            #pragma unroll
            for (int j = 0; j < 8; ++j) St += S->sRedB[j * 65 + kq];
            float inv = 1.f / St;
            #pragma unroll
            for (int i = 0; i < 32; ++i)
                S->sL[(g * 32 + i) * SL_STRIDE + kq] = lv[i] * inv;
        }
        __syncthreads();

        // 3d: F = relu(A @ Wf_tile + bf), immediately att-weighted & reduced.
        {
            u64 acc[4][4];
            #pragma unroll
            for (int p = 0; p < 4; ++p)
                #pragma unroll
                for (int j = 0; j < 4; ++j) acc[p][j] = 0ull;

            #pragma unroll 4
            for (int d = 0; d < Dd; ++d) {
                u64 a0 = *reinterpret_cast<const u64*>(&S->sAT[d * SAT_STRIDE + n0f]);
                u64 a1 = *reinterpret_cast<const u64*>(&S->sAT[d * SAT_STRIDE + n0f + 2]);
                u64 a2 = *reinterpret_cast<const u64*>(&S->sAT[d * SAT_STRIDE + n0f + 4]);
                u64 a3 = *reinterpret_cast<const u64*>(&S->sAT[d * SAT_STRIDE + n0f + 6]);
                ulonglong2 wA = *reinterpret_cast<const ulonglong2*>(&S->sWf2[d * W2_STRIDE + 8 * ktx]);
                ulonglong2 wB = *reinterpret_cast<const ulonglong2*>(&S->sWf2[d * W2_STRIDE + 8 * ktx + 4]);
                ffma2(acc[0][0], a0, wA.x); ffma2(acc[0][1], a0, wA.y);
                ffma2(acc[0][2], a0, wB.x); ffma2(acc[0][3], a0, wB.y);
                ffma2(acc[1][0], a1, wA.x); ffma2(acc[1][1], a1, wA.y);
                ffma2(acc[1][2], a1, wB.x); ffma2(acc[1][3], a1, wB.y);
                ffma2(acc[2][0], a2, wA.x); ffma2(acc[2][1], a2, wA.y);
                ffma2(acc[2][2], a2, wB.x); ffma2(acc[2][3], a2, wB.y);
                ffma2(acc[3][0], a3, wA.x); ffma2(acc[3][1], a3, wA.y);
                ffma2(acc[3][2], a3, wB.x); ffma2(acc[3][3], a3, wB.y);
            }

            float part[4] = {0.f, 0.f, 0.f, 0.f};
            #pragma unroll
            for (int j = 0; j < 4; ++j) {
                float bfj = S->sbf[kt0 + j];
                #pragma unroll
                for (int p = 0; p < 4; ++p) {
                    float v0, v1;
                    unpack2(acc[p][j], v0, v1);
                    float f0 = fmaxf(v0 + bfj, 0.f);
                    float f1 = fmaxf(v1 + bfj, 0.f);
                    float a0 = S->sL[(n0f + 2 * p)     * SL_STRIDE + kt0 + j];
                    float a1 = S->sL[(n0f + 2 * p + 1) * SL_STRIDE + kt0 + j];
                    part[j] = fmaf(a0, f0, part[j]);
                    part[j] = fmaf(a1, f1, part[j]);
                }
            }
            // partials -> sWa2 scratch (weights dead this pass)
            float4 pv = make_float4(part[0], part[1], part[2], part[3]);
            *reinterpret_cast<float4*>(&S->sWa2[tyf * W2_STRIDE + kt0]) = pv;
        }
        __syncthreads();

        if (t < KT) {
            float a = 0.f;
            #pragma unroll
            for (int r = 0; r < 32; ++r) a += S->sWa2[r * W2_STRIDE + t];
            S->sAgg[k0 + t] = a;
        }
        __syncthreads();   // sAgg visible; sL/sWf2/sWa2 free for next pass
    }

    // ---------------- Phase 4: out[b] = relu(agg @ Wl + bl) ----------------
    {
        const int q = t >> 7;        // 0..3 quarter of inner dim
        const int k = t & 127;
        float p4 = 0.f;
        #pragma unroll 8
        for (int j = 0; j < 32; ++j) {
            int jj = q * 32 + j;
            p4 = fmaf(S->sAgg[jj], __ldg(&Wl[jj * LAT + k]), p4);
        }
        S->sWf2[q * W2_STRIDE + k] = p4;
    }
    __syncthreads();
    if (t < LAT) {
        float acc = __ldg(&bl[t]);
        #pragma unroll
        for (int q = 0; q < 4; ++q) acc += S->sWf2[q * W2_STRIDE + t];
        out[(size_t)b * LAT + t] = fmaxf(acc, 0.f);
    }
}

extern "C" void kernel_launch(void* const* d_in, const int* in_sizes, int n_in,
                              void* d_out, int out_size) {
    // metadata order: local_data, neighbor_data, Wc, bc, Wf, bf, Wa, ba, Wl, bl
    // local_data and ba are provably unused (softmax shift-invariance over n).
    const float* nb = (const float*)d_in[1];
    const float* Wc = (const float*)d_in[2];
    const float* bc = (const float*)d_in[3];
    const float* Wf = (const float*)d_in[4];
    const float* bf = (const float*)d_in[5];
    const float* Wa = (const float*)d_in[6];
    const float* Wl = (const float*)d_in[8];
    const float* bl = (const float*)d_in[9];
    float* out = (float*)d_out;

    cudaFuncSetAttribute(arm_fused_kernel,
                         cudaFuncAttributeMaxDynamicSharedMemorySize,
                         (int)sizeof(SmemT));
    arm_fused_kernel<<<Bsz, NTHREADS, sizeof(SmemT)>>>(nb, Wc, bc, Wf, bf, Wa, Wl, bl, out);
}

// round 5
// speedup vs baseline: 1.6371x; 1.6371x over previous
#include <cuda_runtime.h>

// Problem constants
#define Bsz 1024
#define Nn  256
#define Dd  64
#define LAT 128
#define EC  32
#define KT  64              // k-tile per pass
#define NPASS (LAT / KT)    // 2
#define NTHREADS 512

// Shared strides (floats) — derived for conflict-freedom:
//  SAT/SET = 264 : bank(row r, col n) = (8r+n)%32 -> n distinct per warp => CF
//  SW      = 68  : LDS.128 at d*68+4*ktx is contiguous 256B per warp => 2 CF wavefronts
//  SLT     = 262 : 262%32==6 -> n-pair (u64) stores from 16 k-groups land on
//                  16 distinct even bank-pairs => conflict-free
#define SAT_STRIDE 264
#define SET_STRIDE 264
#define SW_STRIDE  68
#define SLT_STRIDE 262

struct SmemT {
    float sAT[Dd * SAT_STRIDE];   // 16896 : A^T[d][n] (persistent)
    float sET[EC * SET_STRIDE];   //  8448 : Ecomm^T[e][n] (persistent)
    float sW [Dd * SW_STRIDE];    //  4352 : Wc (ph2) / Wf tile [d][kt]
    float sWa[EC * SW_STRIDE];    //  2176 : Wa2 tile [e][kt]; then partials scratch
    float sLT[KT * SLT_STRIDE];   // 16768 : logits^T -> att^T in place; ph4 scratch
    float sbc[EC];
    float sbf[KT];
    float sAgg[LAT];
    float sRedA[8 * SW_STRIDE];   // softmax reductions (g x kq)
    float sRedB[8 * SW_STRIDE];
};
// total = 49952 floats = 199808 bytes (< 227KB)

typedef unsigned long long u64;

__device__ __forceinline__ void unpack2(u64 v, float& lo, float& hi) {
    asm("mov.b64 {%0, %1}, %2;" : "=f"(lo), "=f"(hi) : "l"(v));
}
__device__ __forceinline__ u64 pack2(float a, float b) {
    u64 r;
    asm("mov.b64 %0, {%1, %2};" : "=l"(r) : "f"(a), "f"(b));
    return r;
}
// Packed fp32x2 FMA (Blackwell FFMA2): 2x fp32 throughput vs scalar FFMA.
__device__ __forceinline__ void ffma2(u64& d, u64 a, u64 b) {
    asm("fma.rn.f32x2 %0, %1, %2, %0;" : "+l"(d) : "l"(a), "l"(b));
}

__global__ void __launch_bounds__(NTHREADS, 1)
arm_fused_kernel(const float* __restrict__ nb,   // [B,N,D]
                 const float* __restrict__ Wc,   // [D,EC]
                 const float* __restrict__ bc,   // [EC]
                 const float* __restrict__ Wf,   // [D,LAT]
                 const float* __restrict__ bf,   // [LAT]
                 const float* __restrict__ Wa,   // [3EC,LAT] (rows EC..2EC-1 only)
                 const float* __restrict__ Wl,   // [LAT,LAT]
                 const float* __restrict__ bl,   // [LAT]
                 float* __restrict__ out)        // [B,LAT]
{
    extern __shared__ float smem_raw[];
    SmemT* S = reinterpret_cast<SmemT*>(smem_raw);

    const int t = threadIdx.x;
    const int b = blockIdx.x;

    // ---------------- Phase 1: A^T + Wc + bc ----------------
    {
        const float4* nb4 = reinterpret_cast<const float4*>(nb + (size_t)b * Nn * Dd);
        #pragma unroll
        for (int r = 0; r < 8; ++r) {
            int idx = r * NTHREADS + t;        // 0..4095
            int n   = idx & 255;               // 32 distinct n per warp -> CF stores
            int dq  = idx >> 8;                // 0..15
            float4 v = nb4[n * 16 + dq];
            int d0 = dq * 4;
            S->sAT[(d0 + 0) * SAT_STRIDE + n] = v.x;
            S->sAT[(d0 + 1) * SAT_STRIDE + n] = v.y;
            S->sAT[(d0 + 2) * SAT_STRIDE + n] = v.z;
            S->sAT[(d0 + 3) * SAT_STRIDE + n] = v.w;
        }
        // Wc (64x32) plain into sW
        #pragma unroll
        for (int r = 0; r < 4; ++r) {
            int li = r * NTHREADS + t;         // 0..2047
            int d  = li >> 5;
            int e  = li & 31;
            S->sW[d * SW_STRIDE + e] = Wc[d * EC + e];
        }
        if (t < EC) S->sbc[t] = bc[t];
    }
    __syncthreads();

    // ---------------- Phase 2: Ecomm^T = relu(A@Wc+bc)^T  [32e x 256n] ----------------
    {
        const int e0  = (t & 7) * 4;           // 8 e-groups of 4
        const int n02 = (t >> 3) * 4;          // 64 n-groups of 4 (2 pairs)
        u64 acc[2][4];
        #pragma unroll
        for (int p = 0; p < 2; ++p)
            #pragma unroll
            for (int j = 0; j < 4; ++j) acc[p][j] = 0ull;

        #pragma unroll 8
        for (int d = 0; d < Dd; ++d) {
            ulonglong2 a = *reinterpret_cast<const ulonglong2*>(&S->sAT[d * SAT_STRIDE + n02]);
            float4 w = *reinterpret_cast<const float4*>(&S->sW[d * SW_STRIDE + e0]);
            u64 w0 = pack2(w.x, w.x), w1 = pack2(w.y, w.y);
            u64 w2 = pack2(w.z, w.z), w3 = pack2(w.w, w.w);
            ffma2(acc[0][0], a.x, w0); ffma2(acc[0][1], a.x, w1);
            ffma2(acc[0][2], a.x, w2); ffma2(acc[0][3], a.x, w3);
            ffma2(acc[1][0], a.y, w0); ffma2(acc[1][1], a.y, w1);
            ffma2(acc[1][2], a.y, w2); ffma2(acc[1][3], a.y, w3);
        }
        #pragma unroll
        for (int j = 0; j < 4; ++j) {
            float bcj = S->sbc[e0 + j];
            #pragma unroll
            for (int p = 0; p < 2; ++p) {
                float v0, v1;
                unpack2(acc[p][j], v0, v1);
                u64 rv = pack2(fmaxf(v0 + bcj, 0.f), fmaxf(v1 + bcj, 0.f));
                *reinterpret_cast<u64*>(&S->sET[(e0 + j) * SET_STRIDE + n02 + 2 * p]) = rv;
            }
        }
    }
    __syncthreads();

    // ---------------- Phase 3: 2 passes over LAT ----------------
    const int ktx = t & 15;          // 16 k-groups of 4
    const int kt0 = ktx * 4;
    const int tyf = t >> 4;          // 0..31
    const int n0f = tyf * 8;         // 8 n per thread (4 pairs)
    const int kq  = t & 63;          // softmax column within tile
    const int g   = t >> 6;          // softmax n-chunk (8 x 32)

    for (int kp = 0; kp < NPASS; ++kp) {
        const int k0 = kp * KT;

        // 3a: stage Wf tile (64x64), Wa2 tile (32x64), bf tile — plain layout
        #pragma unroll
        for (int r = 0; r < 8; ++r) {
            int li = r * NTHREADS + t;          // 0..4095
            int d  = li >> 6;
            int kk = li & 63;
            S->sW[d * SW_STRIDE + kk] = Wf[d * LAT + k0 + kk];
        }
        #pragma unroll
        for (int r = 0; r < 4; ++r) {
            int li = r * NTHREADS + t;          // 0..2047
            int e  = li >> 6;
            int kk = li & 63;
            S->sWa[e * SW_STRIDE + kk] = Wa[(EC + e) * LAT + k0 + kk];
        }
        if (t < KT) S->sbf[t] = bf[k0 + t];
        __syncthreads();

        // 3b: logits^T = (Ecomm @ Wa2_tile)^T  (bias/self/mean cancel in softmax)
        {
            u64 acc[4][4];
            #pragma unroll
            for (int p = 0; p < 4; ++p)
                #pragma unroll
                for (int j = 0; j < 4; ++j) acc[p][j] = 0ull;

            #pragma unroll 8
            for (int e = 0; e < EC; ++e) {
                ulonglong2 aA = *reinterpret_cast<const ulonglong2*>(&S->sET[e * SET_STRIDE + n0f]);
                ulonglong2 aB = *reinterpret_cast<const ulonglong2*>(&S->sET[e * SET_STRIDE + n0f + 4]);
                float4 w = *reinterpret_cast<const float4*>(&S->sWa[e * SW_STRIDE + kt0]);
                u64 w0 = pack2(w.x, w.x), w1 = pack2(w.y, w.y);
                u64 w2 = pack2(w.z, w.z), w3 = pack2(w.w, w.w);
                ffma2(acc[0][0], aA.x, w0); ffma2(acc[0][1], aA.x, w1);
                ffma2(acc[0][2], aA.x, w2); ffma2(acc[0][3], aA.x, w3);
                ffma2(acc[1][0], aA.y, w0); ffma2(acc[1][1], aA.y, w1);
                ffma2(acc[1][2], aA.y, w2); ffma2(acc[1][3], aA.y, w3);
                ffma2(acc[2][0], aB.x, w0); ffma2(acc[2][1], aB.x, w1);
                ffma2(acc[2][2], aB.x, w2); ffma2(acc[2][3], aB.x, w3);
                ffma2(acc[3][0], aB.y, w0); ffma2(acc[3][1], aB.y, w1);
                ffma2(acc[3][2], aB.y, w2); ffma2(acc[3][3], aB.y, w3);
            }
            // n-packed accs store straight into transposed logits (CF, stride 262)
            #pragma unroll
            for (int j = 0; j < 4; ++j)
                #pragma unroll
                for (int p = 0; p < 4; ++p)
                    *reinterpret_cast<u64*>(&S->sLT[(kt0 + j) * SLT_STRIDE + n0f + 2 * p]) = acc[p][j];
        }
        __syncthreads();

        // 3c: per-column softmax over n=256 in transposed layout (in place)
        {
            float lv[32];
            float m = -1e30f;
            #pragma unroll
            for (int i = 0; i < 32; ++i) {
                lv[i] = S->sLT[kq * SLT_STRIDE + g * 32 + i];
                m = fmaxf(m, lv[i]);
            }
            S->sRedA[g * SW_STRIDE + kq] = m;
            __syncthreads();
            #pragma unroll
            for (int j = 0; j < 8; ++j) m = fmaxf(m, S->sRedA[j * SW_STRIDE + kq]);

            float s = 0.f;
            #pragma unroll
            for (int i = 0; i < 32; ++i) {
                lv[i] = __expf(lv[i] - m);
                s += lv[i];
            }
            S->sRedB[g * SW_STRIDE + kq] = s;
            __syncthreads();
            float St = 0.f;
            #pragma unroll
            for (int j = 0; j < 8; ++j) St += S->sRedB[j * SW_STRIDE + kq];
            float inv = 1.f / St;
            #pragma unroll
            for (int i = 0; i < 32; ++i)
                S->sLT[kq * SLT_STRIDE + g * 32 + i] = lv[i] * inv;
        }
        __syncthreads();

        // 3d: F = relu(A@Wf_tile+bf); weighted sum against att in packed pairs
        {
            u64 acc[4][4];
            #pragma unroll
            for (int p = 0; p < 4; ++p)
                #pragma unroll
                for (int j = 0; j < 4; ++j) acc[p][j] = 0ull;

            #pragma unroll 8
            for (int d = 0; d < Dd; ++d) {
                ulonglong2 aA = *reinterpret_cast<const ulonglong2*>(&S->sAT[d * SAT_STRIDE + n0f]);
                ulonglong2 aB = *reinterpret_cast<const ulonglong2*>(&S->sAT[d * SAT_STRIDE + n0f + 4]);
                float4 w = *reinterpret_cast<const float4*>(&S->sW[d * SW_STRIDE + kt0]);
                u64 w0 = pack2(w.x, w.x), w1 = pack2(w.y, w.y);
                u64 w2 = pack2(w.z, w.z), w3 = pack2(w.w, w.w);
                ffma2(acc[0][0], aA.x, w0); ffma2(acc[0][1], aA.x, w1);
                ffma2(acc[0][2], aA.x, w2); ffma2(acc[0][3], aA.x, w3);
                ffma2(acc[1][0], aA.y, w0); ffma2(acc[1][1], aA.y, w1);
                ffma2(acc[1][2], aA.y, w2); ffma2(acc[1][3], aA.y, w3);
                ffma2(acc[2][0], aB.x, w0); ffma2(acc[2][1], aB.x, w1);
                ffma2(acc[2][2], aB.x, w2); ffma2(acc[2][3], aB.x, w3);
                ffma2(acc[3][0], aB.y, w0); ffma2(acc[3][1], aB.y, w1);
                ffma2(acc[3][2], aB.y, w2); ffma2(acc[3][3], aB.y, w3);
            }

            u64 partP[4] = {0ull, 0ull, 0ull, 0ull};
            #pragma unroll
            for (int j = 0; j < 4; ++j) {
                float bfj = S->sbf[kt0 + j];
                u64 bfp = pack2(bfj, bfj);
                #pragma unroll
                for (int p = 0; p < 4; ++p) {
                    float v0, v1;
                    unpack2(acc[p][j], v0, v1);
                    u64 fpair = pack2(fmaxf(v0 + bfj, 0.f), fmaxf(v1 + bfj, 0.f));
                    (void)bfp;
                    u64 apair = *reinterpret_cast<const u64*>(
                        &S->sLT[(kt0 + j) * SLT_STRIDE + n0f + 2 * p]);
                    ffma2(partP[j], apair, fpair);
                }
            }
            float part[4];
            #pragma unroll
            for (int j = 0; j < 4; ++j) {
                float p0, p1;
                unpack2(partP[j], p0, p1);
                part[j] = p0 + p1;
            }
            // partials -> sWa scratch (Wa2 tile dead after 3b)
            *reinterpret_cast<float4*>(&S->sWa[tyf * SW_STRIDE + kt0]) =
                make_float4(part[0], part[1], part[2], part[3]);
        }
        __syncthreads();

        if (t < KT) {
            float a = 0.f;
            #pragma unroll
            for (int r = 0; r < 32; ++r) a += S->sWa[r * SW_STRIDE + t];
            S->sAgg[k0 + t] = a;
        }
        __syncthreads();
    }

    // ---------------- Phase 4: out[b] = relu(agg @ Wl + bl) ----------------
    {
        const int q = t >> 7;        // 0..3 quarter of inner dim
        const int k = t & 127;
        float p4 = 0.f;
        #pragma unroll 8
        for (int j = 0; j < 32; ++j) {
            int jj = q * 32 + j;
            p4 = fmaf(S->sAgg[jj], __ldg(&Wl[jj * LAT + k]), p4);
        }
        S->sLT[q * SLT_STRIDE + k] = p4;   // sLT free after last pass
    }
    __syncthreads();
    if (t < LAT) {
        float acc = __ldg(&bl[t]);
        #pragma unroll
        for (int q = 0; q < 4; ++q) acc += S->sLT[q * SLT_STRIDE + t];
        out[(size_t)b * LAT + t] = fmaxf(acc, 0.f);
    }
}

extern "C" void kernel_launch(void* const* d_in, const int* in_sizes, int n_in,
                              void* d_out, int out_size) {
    // metadata order: local_data, neighbor_data, Wc, bc, Wf, bf, Wa, ba, Wl, bl
    // local_data and ba are provably unused (softmax shift-invariance over n).
    const float* nb = (const float*)d_in[1];
    const float* Wc = (const float*)d_in[2];
    const float* bc = (const float*)d_in[3];
    const float* Wf = (const float*)d_in[4];
    const float* bf = (const float*)d_in[5];
    const float* Wa = (const float*)d_in[6];
    const float* Wl = (const float*)d_in[8];
    const float* bl = (const float*)d_in[9];
    float* out = (float*)d_out;

    cudaFuncSetAttribute(arm_fused_kernel,
                         cudaFuncAttributeMaxDynamicSharedMemorySize,
                         (int)sizeof(SmemT));
    arm_fused_kernel<<<Bsz, NTHREADS, sizeof(SmemT)>>>(nb, Wc, bc, Wf, bf, Wa, Wl, bl, out);
}